// round 8
// baseline (speedup 1.0000x reference)
#include <cuda_runtime.h>
#include <cuda_fp16.h>

#define DD 64
#define NMAX 100000
#define EMAX 1600000
#define NB_SCAN 240

// -------- scratch (static device globals; zero-initialized at load) --------
__device__ __half g_th[NMAX * DD];     // t = h @ W (half)
__device__ __half g_hh[NMAX * DD];     // h after agg (half)
__device__ int    g_deg[NMAX];         // zero at entry; reset by k_scatter each call
__device__ int    g_offs[NMAX + 1];
__device__ int    g_cursor[NMAX];
__device__ int    g_srcs[EMAX];
__device__ float  g_invdeg[NMAX];
__device__ int    g_bsum[NB_SCAN];

// -------- one-time stream/event setup (host-side only) --------
struct HxStreams {
    cudaStream_t s2;
    cudaEvent_t evFork, evJoin;
    HxStreams() {
        cudaStreamCreateWithFlags(&s2, cudaStreamNonBlocking);
        cudaEventCreateWithFlags(&evFork, cudaEventDisableTiming);
        cudaEventCreateWithFlags(&evJoin, cudaEventDisableTiming);
    }
};
static HxStreams g_hx;

#define MMA16816(c0,c1,c2,c3,a0,a1,a2,a3,b0,b1) \
    asm volatile("mma.sync.aligned.m16n8k16.row.col.f32.f16.f16.f32 " \
        "{%0,%1,%2,%3}, {%4,%5,%6,%7}, {%8,%9}, {%0,%1,%2,%3};" \
        : "+f"(c0), "+f"(c1), "+f"(c2), "+f"(c3) \
        : "r"(a0), "r"(a1), "r"(a2), "r"(a3), "r"(b0), "r"(b1))

// -------- degree count: 8 edges/thread, batched atomics --------
__global__ void k_deg(const int* __restrict__ dst, int e) {
    int i = blockIdx.x * blockDim.x + threadIdx.x;
    int base = i * 8;
    if (base + 8 <= e) {
        int4 d0 = *(const int4*)(dst + base);
        int4 d1 = *(const int4*)(dst + base + 4);
        atomicAdd(&g_deg[d0.x], 1); atomicAdd(&g_deg[d0.y], 1);
        atomicAdd(&g_deg[d0.z], 1); atomicAdd(&g_deg[d0.w], 1);
        atomicAdd(&g_deg[d1.x], 1); atomicAdd(&g_deg[d1.y], 1);
        atomicAdd(&g_deg[d1.z], 1); atomicAdd(&g_deg[d1.w], 1);
    } else {
        for (int j = base; j < e; ++j) atomicAdd(&g_deg[dst[j]], 1);
    }
}

// -------- scan phase A: per-block sums --------
__global__ void k_scan_a(int n) {
    __shared__ int s[256];
    int b = blockIdx.x;
    int ch = (n + NB_SCAN - 1) / NB_SCAN;
    int lo = b * ch, hi = min(n, lo + ch);
    int t = threadIdx.x;
    int acc = 0;
    for (int i = lo + t; i < hi; i += 256) acc += g_deg[i];
    s[t] = acc;
    __syncthreads();
    for (int off = 128; off > 0; off >>= 1) {
        if (t < off) s[t] += s[t + off];
        __syncthreads();
    }
    if (t == 0) g_bsum[b] = s[0];
}

// -------- scan phase C: warp-shuffle scan --------
__global__ void k_scan_c(int n, int e) {
    __shared__ int wsum[8];
    __shared__ int sCarry;
    int b = blockIdx.x;
    int t = threadIdx.x;
    int lane = t & 31, wid = t >> 5;
    if (b == 0 && t == 0) g_offs[n] = e;

    if (wid == 0) {
        int acc = 0;
        for (int i = lane; i < b; i += 32) acc += g_bsum[i];
        #pragma unroll
        for (int off = 16; off > 0; off >>= 1)
            acc += __shfl_down_sync(0xFFFFFFFFu, acc, off);
        if (lane == 0) sCarry = acc;
    }
    __syncthreads();
    int carry = sCarry;

    int ch = (n + NB_SCAN - 1) / NB_SCAN;
    int lo = b * ch, hi = min(n, lo + ch);
    for (int base = lo; base < hi; base += 256) {
        int idx = base + t;
        int v = (idx < hi) ? g_deg[idx] : 0;
        int sc = v;
        #pragma unroll
        for (int off = 1; off < 32; off <<= 1) {
            int x = __shfl_up_sync(0xFFFFFFFFu, sc, off);
            if (lane >= off) sc += x;
        }
        if (lane == 31) wsum[wid] = sc;
        __syncthreads();
        int woff = 0;
        if (wid > 0) {
            #pragma unroll
            for (int w = 0; w < 7; ++w) if (w < wid) woff += wsum[w];
        }
        int total = 0;
        #pragma unroll
        for (int w = 0; w < 8; ++w) total += wsum[w];
        if (idx < hi) {
            int exc = carry + woff + sc - v;
            g_offs[idx]   = exc;
            g_cursor[idx] = exc;
            g_invdeg[idx] = 1.0f / (float)(v > 0 ? v : 1);
        }
        carry += total;
        __syncthreads();
    }
}

// -------- scatter edges into CSR: 8 edges/thread; resets g_deg --------
__global__ void k_scatter(const int* __restrict__ src, const int* __restrict__ dst,
                          int e, int n) {
    int i = blockIdx.x * blockDim.x + threadIdx.x;
    int base = i * 8;
    if (base + 8 <= e) {
        int4 s0 = *(const int4*)(src + base);
        int4 s1 = *(const int4*)(src + base + 4);
        int4 d0 = *(const int4*)(dst + base);
        int4 d1 = *(const int4*)(dst + base + 4);
        int p[8];
        p[0] = atomicAdd(&g_cursor[d0.x], 1);
        p[1] = atomicAdd(&g_cursor[d0.y], 1);
        p[2] = atomicAdd(&g_cursor[d0.z], 1);
        p[3] = atomicAdd(&g_cursor[d0.w], 1);
        p[4] = atomicAdd(&g_cursor[d1.x], 1);
        p[5] = atomicAdd(&g_cursor[d1.y], 1);
        p[6] = atomicAdd(&g_cursor[d1.z], 1);
        p[7] = atomicAdd(&g_cursor[d1.w], 1);
        g_srcs[p[0]] = s0.x; g_srcs[p[1]] = s0.y;
        g_srcs[p[2]] = s0.z; g_srcs[p[3]] = s0.w;
        g_srcs[p[4]] = s1.x; g_srcs[p[5]] = s1.y;
        g_srcs[p[6]] = s1.z; g_srcs[p[7]] = s1.w;
    } else {
        for (int j = base; j < e; ++j)
            g_srcs[atomicAdd(&g_cursor[dst[j]], 1)] = src[j];
    }
    if (i < n) g_deg[i] = 0;
}

// -------- tensor-core GEMM: tout(half) = A @ W --------
// A = emb[tok[row]] (float, layer 1) or hin (half, layer 2).
// 128 threads (4 warps), tile M=64 N=64 K=64; warp w: rows [16w,16w+16).
// mma.m16n8k16, fp32 accumulate.
__global__ void k_gemm_mma(const __half* __restrict__ hin, const int* __restrict__ tok,
                           const float* __restrict__ emb, const float* __restrict__ W,
                           __half* __restrict__ tout, int n) {
    __shared__ __half sA[64 * 72];
    __shared__ __half sW[64 * 72];     // transposed: sW[n*72 + k]
    int t = threadIdx.x;
    int row0 = blockIdx.x * 64;

    // W (float [k][n]) -> sW[n][k] half
    #pragma unroll
    for (int it = 0; it < 8; ++it) {
        int flat = t + it * 128;       // float4 over 64x16
        int k  = flat >> 4;
        int n4 = (flat & 15) * 4;
        float4 w = ((const float4*)W)[flat];
        sW[(n4 + 0) * 72 + k] = __float2half(w.x);
        sW[(n4 + 1) * 72 + k] = __float2half(w.y);
        sW[(n4 + 2) * 72 + k] = __float2half(w.z);
        sW[(n4 + 3) * 72 + k] = __float2half(w.w);
    }
    // A tile -> sA (row-major, half)
    if (tok) {
        #pragma unroll
        for (int it = 0; it < 8; ++it) {
            int flat = t + it * 128;   // float4 over 64x16
            int r = flat >> 4, c4 = flat & 15;
            int gr = row0 + r;
            float4 v = make_float4(0.f, 0.f, 0.f, 0.f);
            if (gr < n) v = ((const float4*)emb)[tok[gr] * 16 + c4];
            *(__half2*)&sA[r * 72 + c4 * 4]     = __floats2half2_rn(v.x, v.y);
            *(__half2*)&sA[r * 72 + c4 * 4 + 2] = __floats2half2_rn(v.z, v.w);
        }
    } else {
        #pragma unroll
        for (int it = 0; it < 4; ++it) {
            int flat = t + it * 128;   // uint4 over 64x8
            int r = flat >> 3, q = flat & 7;
            int gr = row0 + r;
            uint4 v = make_uint4(0u, 0u, 0u, 0u);
            if (gr < n) v = ((const uint4*)hin)[gr * 8 + q];
            *(uint2*)&sA[r * 72 + q * 8]     = make_uint2(v.x, v.y);
            *(uint2*)&sA[r * 72 + q * 8 + 4] = make_uint2(v.z, v.w);
        }
    }
    __syncthreads();

    int w = t >> 5, lane = t & 31;
    int g = lane >> 2, t2 = lane & 3;
    int R = w * 16;
    float acc[8][4];
    #pragma unroll
    for (int i = 0; i < 8; ++i)
        #pragma unroll
        for (int j = 0; j < 4; ++j) acc[i][j] = 0.f;

    #pragma unroll
    for (int kt = 0; kt < 4; ++kt) {
        int c = kt * 16 + t2 * 2;
        unsigned a0 = *(unsigned*)&sA[(R + g)     * 72 + c];
        unsigned a1 = *(unsigned*)&sA[(R + g + 8) * 72 + c];
        unsigned a2 = *(unsigned*)&sA[(R + g)     * 72 + c + 8];
        unsigned a3 = *(unsigned*)&sA[(R + g + 8) * 72 + c + 8];
        #pragma unroll
        for (int nt = 0; nt < 8; ++nt) {
            unsigned b0 = *(unsigned*)&sW[(nt * 8 + g) * 72 + c];
            unsigned b1 = *(unsigned*)&sW[(nt * 8 + g) * 72 + c + 8];
            MMA16816(acc[nt][0], acc[nt][1], acc[nt][2], acc[nt][3],
                     a0, a1, a2, a3, b0, b1);
        }
    }

    int r1 = row0 + R + g;
    int r2 = r1 + 8;
    #pragma unroll
    for (int nt = 0; nt < 8; ++nt) {
        int col = nt * 8 + t2 * 2;
        if (r1 < n) *(__half2*)&tout[r1 * 64 + col] = __floats2half2_rn(acc[nt][0], acc[nt][1]);
        if (r2 < n) *(__half2*)&tout[r2 * 64 + col] = __floats2half2_rn(acc[nt][2], acc[nt][3]);
    }
}

// -------- aggregate: hout(half) = relu(invdeg * sum_{CSR} t_half[src] + b) --------
// 8 threads/node; direct index loads, 8-edge unroll, L2-only gathers.
__global__ void k_agg(const __half* __restrict__ tin, const float* __restrict__ b,
                      __half* __restrict__ hout, int n) {
    int node = blockIdx.x * 32 + (threadIdx.x >> 3);
    int d8 = threadIdx.x & 7;
    if (node >= n) return;
    int s0 = g_offs[node], s1 = g_offs[node + 1];
    const uint4* t4 = (const uint4*)tin;

    float2 a0 = make_float2(0.f, 0.f), a1 = a0, a2 = a0, a3 = a0;
    int e = s0;
    for (; e + 8 <= s1; e += 8) {
        uint4 v[8];
        #pragma unroll
        for (int q = 0; q < 8; ++q) {
            int sn = g_srcs[e + q];
            v[q] = __ldcg(&t4[sn * 8 + d8]);
        }
        #pragma unroll
        for (int q = 0; q < 8; ++q) {
            float2 f0 = __half22float2(*(__half2*)&v[q].x);
            float2 f1 = __half22float2(*(__half2*)&v[q].y);
            float2 f2 = __half22float2(*(__half2*)&v[q].z);
            float2 f3 = __half22float2(*(__half2*)&v[q].w);
            a0.x += f0.x; a0.y += f0.y;
            a1.x += f1.x; a1.y += f1.y;
            a2.x += f2.x; a2.y += f2.y;
            a3.x += f3.x; a3.y += f3.y;
        }
    }
    for (; e < s1; ++e) {
        uint4 v = __ldcg(&t4[g_srcs[e] * 8 + d8]);
        float2 f0 = __half22float2(*(__half2*)&v.x);
        float2 f1 = __half22float2(*(__half2*)&v.y);
        float2 f2 = __half22float2(*(__half2*)&v.z);
        float2 f3 = __half22float2(*(__half2*)&v.w);
        a0.x += f0.x; a0.y += f0.y;
        a1.x += f1.x; a1.y += f1.y;
        a2.x += f2.x; a2.y += f2.y;
        a3.x += f3.x; a3.y += f3.y;
    }

    float id = g_invdeg[node];
    float4 b0 = ((const float4*)b)[d8 * 2];
    float4 b1 = ((const float4*)b)[d8 * 2 + 1];
    __half2 p0 = __floats2half2_rn(fmaxf(a0.x * id + b0.x, 0.f), fmaxf(a0.y * id + b0.y, 0.f));
    __half2 p1 = __floats2half2_rn(fmaxf(a1.x * id + b0.z, 0.f), fmaxf(a1.y * id + b0.w, 0.f));
    __half2 p2 = __floats2half2_rn(fmaxf(a2.x * id + b1.x, 0.f), fmaxf(a2.y * id + b1.y, 0.f));
    __half2 p3 = __floats2half2_rn(fmaxf(a3.x * id + b1.z, 0.f), fmaxf(a3.y * id + b1.w, 0.f));
    uint4 pk;
    pk.x = *(unsigned*)&p0; pk.y = *(unsigned*)&p1;
    pk.z = *(unsigned*)&p2; pk.w = *(unsigned*)&p3;
    ((uint4*)hout)[node * 8 + d8] = pk;
}

// -------- fused mean-pool + classifier: one block per graph --------
__global__ void k_poolclass(const __half* __restrict__ h, const int* __restrict__ gid,
                            const float* __restrict__ Wc, const float* __restrict__ bc,
                            float* __restrict__ out, int n, int C) {
    int g = blockIdx.x;
    __shared__ int sLo, sHi;
    if (threadIdx.x == 0) {
        int lo = 0, hi = n;
        while (lo < hi) { int m = (lo + hi) >> 1; if (gid[m] < g) lo = m + 1; else hi = m; }
        sLo = lo;
        int lo2 = lo, hi2 = n;
        while (lo2 < hi2) { int m = (lo2 + hi2) >> 1; if (gid[m] < g + 1) lo2 = m + 1; else hi2 = m; }
        sHi = lo2;
    }
    __syncthreads();
    int lo = sLo, hi = sHi;
    int d  = threadIdx.x & 63;
    int rg = threadIdx.x >> 6;               // 0..7 (512 threads)
    float acc = 0.f;
    for (int i = lo + rg; i < hi; i += 8) acc += __half2float(h[i * 64 + d]);
    __shared__ float sm[512];
    __shared__ float mean[64];
    sm[threadIdx.x] = acc;
    __syncthreads();
    if (threadIdx.x < 64) {
        float s = 0.f;
        #pragma unroll
        for (int k = 0; k < 8; ++k) s += sm[k * 64 + d];
        float cnt = (float)(hi - lo);
        mean[d] = s / fmaxf(cnt, 1.f);
    }
    __syncthreads();
    if ((int)threadIdx.x < C) {
        int c = threadIdx.x;
        float s = 0.f;
        #pragma unroll
        for (int dd = 0; dd < 64; ++dd) s += mean[dd] * Wc[dd * C + c];
        out[g * C + c] = s + bc[c];
    }
}

extern "C" void kernel_launch(void* const* d_in, const int* in_sizes, int n_in,
                              void* d_out, int out_size) {
    const int*   tokens   = (const int*)d_in[0];
    const int*   edge_src = (const int*)d_in[1];
    const int*   edge_dst = (const int*)d_in[2];
    const int*   graph_id = (const int*)d_in[3];
    const float* emb      = (const float*)d_in[4];
    const float* W1       = (const float*)d_in[5];
    const float* b1       = (const float*)d_in[6];
    const float* W2       = (const float*)d_in[7];
    const float* b2       = (const float*)d_in[8];
    const float* Wc       = (const float*)d_in[9];
    const float* bc       = (const float*)d_in[10];
    float* out = (float*)d_out;

    int N = in_sizes[0];
    int E = in_sizes[1];
    int C = in_sizes[10];
    int G = out_size / C;

    __half *tb, *hb;
    cudaGetSymbolAddress((void**)&tb, g_th);
    cudaGetSymbolAddress((void**)&hb, g_hh);

    int e8 = (E + 7) / 8;

    // Fork: GEMM-1 (fused embedding) on side stream, CSR build on main stream.
    cudaEventRecord(g_hx.evFork, 0);
    cudaStreamWaitEvent(g_hx.s2, g_hx.evFork, 0);
    k_gemm_mma<<<(N + 63) / 64, 128, 0, g_hx.s2>>>(nullptr, tokens, emb, W1, tb, N);
    cudaEventRecord(g_hx.evJoin, g_hx.s2);

    // CSR build (main stream)
    k_deg    <<<(e8 + 255) / 256, 256>>>(edge_dst, E);
    k_scan_a <<<NB_SCAN, 256>>>(N);
    k_scan_c <<<NB_SCAN, 256>>>(N, E);
    k_scatter<<<(e8 + 255) / 256, 256>>>(edge_src, edge_dst, E, N);

    // Join: agg-1 needs both CSR and GEMM-1 output.
    cudaStreamWaitEvent(0, g_hx.evJoin, 0);
    k_agg<<<(N + 31) / 32, 256>>>(tb, b1, hb, N);

    // layer 2
    k_gemm_mma<<<(N + 63) / 64, 128>>>(hb, nullptr, nullptr, W2, tb, N);
    k_agg<<<(N + 31) / 32, 256>>>(tb, b2, hb, N);

    // fused pool + classify
    k_poolclass<<<G, 512>>>(hb, graph_id, Wc, bc, out, N, C);
}

// round 9
// speedup vs baseline: 1.0033x; 1.0033x over previous
#include <cuda_runtime.h>
#include <cuda_fp16.h>

#define DD 64
#define NMAX 100000
#define EMAX 1600000
#define NB_SCAN 240

// -------- scratch (static device globals; zero-initialized at load) --------
__device__ __half g_th[NMAX * DD];     // t = h @ W (half)
__device__ __half g_hh[NMAX * DD];     // h after agg (half)
__device__ int    g_deg[NMAX];         // zero at entry; reset by k_scatter each call
__device__ int    g_offs[NMAX + 1];
__device__ int    g_cursor[NMAX];
__device__ int    g_srcs[EMAX];
__device__ float  g_invdeg[NMAX];
__device__ int    g_bsum[NB_SCAN];

// -------- one-time stream/event setup (host-side only) --------
struct HxStreams {
    cudaStream_t s2;
    cudaEvent_t evFork, evJoin;
    HxStreams() {
        cudaStreamCreateWithFlags(&s2, cudaStreamNonBlocking);
        cudaEventCreateWithFlags(&evFork, cudaEventDisableTiming);
        cudaEventCreateWithFlags(&evJoin, cudaEventDisableTiming);
    }
};
static HxStreams g_hx;

#define MMA16816(c0,c1,c2,c3,a0,a1,a2,a3,b0,b1) \
    asm volatile("mma.sync.aligned.m16n8k16.row.col.f32.f16.f16.f32 " \
        "{%0,%1,%2,%3}, {%4,%5,%6,%7}, {%8,%9}, {%0,%1,%2,%3};" \
        : "+f"(c0), "+f"(c1), "+f"(c2), "+f"(c3) \
        : "r"(a0), "r"(a1), "r"(a2), "r"(a3), "r"(b0), "r"(b1))

// -------- degree count: 8 edges/thread, batched atomics --------
__global__ void k_deg(const int* __restrict__ dst, int e) {
    int i = blockIdx.x * blockDim.x + threadIdx.x;
    int base = i * 8;
    if (base + 8 <= e) {
        int4 d0 = *(const int4*)(dst + base);
        int4 d1 = *(const int4*)(dst + base + 4);
        atomicAdd(&g_deg[d0.x], 1); atomicAdd(&g_deg[d0.y], 1);
        atomicAdd(&g_deg[d0.z], 1); atomicAdd(&g_deg[d0.w], 1);
        atomicAdd(&g_deg[d1.x], 1); atomicAdd(&g_deg[d1.y], 1);
        atomicAdd(&g_deg[d1.z], 1); atomicAdd(&g_deg[d1.w], 1);
    } else {
        for (int j = base; j < e; ++j) atomicAdd(&g_deg[dst[j]], 1);
    }
}

// -------- scan phase A: per-block sums --------
__global__ void k_scan_a(int n) {
    __shared__ int s[256];
    int b = blockIdx.x;
    int ch = (n + NB_SCAN - 1) / NB_SCAN;
    int lo = b * ch, hi = min(n, lo + ch);
    int t = threadIdx.x;
    int acc = 0;
    for (int i = lo + t; i < hi; i += 256) acc += g_deg[i];
    s[t] = acc;
    __syncthreads();
    for (int off = 128; off > 0; off >>= 1) {
        if (t < off) s[t] += s[t + off];
        __syncthreads();
    }
    if (t == 0) g_bsum[b] = s[0];
}

// -------- scan phase C: warp-shuffle scan --------
__global__ void k_scan_c(int n, int e) {
    __shared__ int wsum[8];
    __shared__ int sCarry;
    int b = blockIdx.x;
    int t = threadIdx.x;
    int lane = t & 31, wid = t >> 5;
    if (b == 0 && t == 0) g_offs[n] = e;

    if (wid == 0) {
        int acc = 0;
        for (int i = lane; i < b; i += 32) acc += g_bsum[i];
        #pragma unroll
        for (int off = 16; off > 0; off >>= 1)
            acc += __shfl_down_sync(0xFFFFFFFFu, acc, off);
        if (lane == 0) sCarry = acc;
    }
    __syncthreads();
    int carry = sCarry;

    int ch = (n + NB_SCAN - 1) / NB_SCAN;
    int lo = b * ch, hi = min(n, lo + ch);
    for (int base = lo; base < hi; base += 256) {
        int idx = base + t;
        int v = (idx < hi) ? g_deg[idx] : 0;
        int sc = v;
        #pragma unroll
        for (int off = 1; off < 32; off <<= 1) {
            int x = __shfl_up_sync(0xFFFFFFFFu, sc, off);
            if (lane >= off) sc += x;
        }
        if (lane == 31) wsum[wid] = sc;
        __syncthreads();
        int woff = 0;
        if (wid > 0) {
            #pragma unroll
            for (int w = 0; w < 7; ++w) if (w < wid) woff += wsum[w];
        }
        int total = 0;
        #pragma unroll
        for (int w = 0; w < 8; ++w) total += wsum[w];
        if (idx < hi) {
            int exc = carry + woff + sc - v;
            g_offs[idx]   = exc;
            g_cursor[idx] = exc;
            g_invdeg[idx] = 1.0f / (float)(v > 0 ? v : 1);
        }
        carry += total;
        __syncthreads();
    }
}

// -------- scatter edges into CSR: 8 edges/thread; resets g_deg --------
__global__ void k_scatter(const int* __restrict__ src, const int* __restrict__ dst,
                          int e, int n) {
    int i = blockIdx.x * blockDim.x + threadIdx.x;
    int base = i * 8;
    if (base + 8 <= e) {
        int4 s0 = *(const int4*)(src + base);
        int4 s1 = *(const int4*)(src + base + 4);
        int4 d0 = *(const int4*)(dst + base);
        int4 d1 = *(const int4*)(dst + base + 4);
        int p[8];
        p[0] = atomicAdd(&g_cursor[d0.x], 1);
        p[1] = atomicAdd(&g_cursor[d0.y], 1);
        p[2] = atomicAdd(&g_cursor[d0.z], 1);
        p[3] = atomicAdd(&g_cursor[d0.w], 1);
        p[4] = atomicAdd(&g_cursor[d1.x], 1);
        p[5] = atomicAdd(&g_cursor[d1.y], 1);
        p[6] = atomicAdd(&g_cursor[d1.z], 1);
        p[7] = atomicAdd(&g_cursor[d1.w], 1);
        g_srcs[p[0]] = s0.x; g_srcs[p[1]] = s0.y;
        g_srcs[p[2]] = s0.z; g_srcs[p[3]] = s0.w;
        g_srcs[p[4]] = s1.x; g_srcs[p[5]] = s1.y;
        g_srcs[p[6]] = s1.z; g_srcs[p[7]] = s1.w;
    } else {
        for (int j = base; j < e; ++j)
            g_srcs[atomicAdd(&g_cursor[dst[j]], 1)] = src[j];
    }
    if (i < n) g_deg[i] = 0;
}

// -------- tensor-core GEMM: tout(half) = A @ W --------
// A = emb[tok[row]] (float, layer 1) or hin (half, layer 2).
// 128 threads (4 warps), tile M=64 N=64 K=64; warp w: rows [16w,16w+16).
// mma.m16n8k16, fp32 accumulate.
__global__ void k_gemm_mma(const __half* __restrict__ hin, const int* __restrict__ tok,
                           const float* __restrict__ emb, const float* __restrict__ W,
                           __half* __restrict__ tout, int n) {
    __shared__ __half sA[64 * 72];
    __shared__ __half sW[64 * 72];     // transposed: sW[n*72 + k]
    int t = threadIdx.x;
    int row0 = blockIdx.x * 64;

    // W (float [k][n]) -> sW[n][k] half
    #pragma unroll
    for (int it = 0; it < 8; ++it) {
        int flat = t + it * 128;       // float4 over 64x16
        int k  = flat >> 4;
        int n4 = (flat & 15) * 4;
        float4 w = ((const float4*)W)[flat];
        sW[(n4 + 0) * 72 + k] = __float2half(w.x);
        sW[(n4 + 1) * 72 + k] = __float2half(w.y);
        sW[(n4 + 2) * 72 + k] = __float2half(w.z);
        sW[(n4 + 3) * 72 + k] = __float2half(w.w);
    }
    // A tile -> sA (row-major, half)
    if (tok) {
        #pragma unroll
        for (int it = 0; it < 8; ++it) {
            int flat = t + it * 128;   // float4 over 64x16
            int r = flat >> 4, c4 = flat & 15;
            int gr = row0 + r;
            float4 v = make_float4(0.f, 0.f, 0.f, 0.f);
            if (gr < n) v = ((const float4*)emb)[tok[gr] * 16 + c4];
            *(__half2*)&sA[r * 72 + c4 * 4]     = __floats2half2_rn(v.x, v.y);
            *(__half2*)&sA[r * 72 + c4 * 4 + 2] = __floats2half2_rn(v.z, v.w);
        }
    } else {
        #pragma unroll
        for (int it = 0; it < 4; ++it) {
            int flat = t + it * 128;   // uint4 over 64x8
            int r = flat >> 3, q = flat & 7;
            int gr = row0 + r;
            uint4 v = make_uint4(0u, 0u, 0u, 0u);
            if (gr < n) v = ((const uint4*)hin)[gr * 8 + q];
            *(uint2*)&sA[r * 72 + q * 8]     = make_uint2(v.x, v.y);
            *(uint2*)&sA[r * 72 + q * 8 + 4] = make_uint2(v.z, v.w);
        }
    }
    __syncthreads();

    int w = t >> 5, lane = t & 31;
    int g = lane >> 2, t2 = lane & 3;
    int R = w * 16;
    float acc[8][4];
    #pragma unroll
    for (int i = 0; i < 8; ++i)
        #pragma unroll
        for (int j = 0; j < 4; ++j) acc[i][j] = 0.f;

    #pragma unroll
    for (int kt = 0; kt < 4; ++kt) {
        int c = kt * 16 + t2 * 2;
        unsigned a0 = *(unsigned*)&sA[(R + g)     * 72 + c];
        unsigned a1 = *(unsigned*)&sA[(R + g + 8) * 72 + c];
        unsigned a2 = *(unsigned*)&sA[(R + g)     * 72 + c + 8];
        unsigned a3 = *(unsigned*)&sA[(R + g + 8) * 72 + c + 8];
        #pragma unroll
        for (int nt = 0; nt < 8; ++nt) {
            unsigned b0 = *(unsigned*)&sW[(nt * 8 + g) * 72 + c];
            unsigned b1 = *(unsigned*)&sW[(nt * 8 + g) * 72 + c + 8];
            MMA16816(acc[nt][0], acc[nt][1], acc[nt][2], acc[nt][3],
                     a0, a1, a2, a3, b0, b1);
        }
    }

    int r1 = row0 + R + g;
    int r2 = r1 + 8;
    #pragma unroll
    for (int nt = 0; nt < 8; ++nt) {
        int col = nt * 8 + t2 * 2;
        if (r1 < n) *(__half2*)&tout[r1 * 64 + col] = __floats2half2_rn(acc[nt][0], acc[nt][1]);
        if (r2 < n) *(__half2*)&tout[r2 * 64 + col] = __floats2half2_rn(acc[nt][2], acc[nt][3]);
    }
}

// -------- aggregate: hout(half) = relu(invdeg * sum_{CSR} t_half[src] + b) --------
// 8 threads/node; direct index loads, 8-edge unroll, L2-only gathers.
__global__ void k_agg(const __half* __restrict__ tin, const float* __restrict__ b,
                      __half* __restrict__ hout, int n) {
    int node = blockIdx.x * 32 + (threadIdx.x >> 3);
    int d8 = threadIdx.x & 7;
    if (node >= n) return;
    int s0 = g_offs[node], s1 = g_offs[node + 1];
    const uint4* t4 = (const uint4*)tin;

    float2 a0 = make_float2(0.f, 0.f), a1 = a0, a2 = a0, a3 = a0;
    int e = s0;
    for (; e + 8 <= s1; e += 8) {
        uint4 v[8];
        #pragma unroll
        for (int q = 0; q < 8; ++q) {
            int sn = g_srcs[e + q];
            v[q] = __ldcg(&t4[sn * 8 + d8]);
        }
        #pragma unroll
        for (int q = 0; q < 8; ++q) {
            float2 f0 = __half22float2(*(__half2*)&v[q].x);
            float2 f1 = __half22float2(*(__half2*)&v[q].y);
            float2 f2 = __half22float2(*(__half2*)&v[q].z);
            float2 f3 = __half22float2(*(__half2*)&v[q].w);
            a0.x += f0.x; a0.y += f0.y;
            a1.x += f1.x; a1.y += f1.y;
            a2.x += f2.x; a2.y += f2.y;
            a3.x += f3.x; a3.y += f3.y;
        }
    }
    for (; e < s1; ++e) {
        uint4 v = __ldcg(&t4[g_srcs[e] * 8 + d8]);
        float2 f0 = __half22float2(*(__half2*)&v.x);
        float2 f1 = __half22float2(*(__half2*)&v.y);
        float2 f2 = __half22float2(*(__half2*)&v.z);
        float2 f3 = __half22float2(*(__half2*)&v.w);
        a0.x += f0.x; a0.y += f0.y;
        a1.x += f1.x; a1.y += f1.y;
        a2.x += f2.x; a2.y += f2.y;
        a3.x += f3.x; a3.y += f3.y;
    }

    float id = g_invdeg[node];
    float4 b0 = ((const float4*)b)[d8 * 2];
    float4 b1 = ((const float4*)b)[d8 * 2 + 1];
    __half2 p0 = __floats2half2_rn(fmaxf(a0.x * id + b0.x, 0.f), fmaxf(a0.y * id + b0.y, 0.f));
    __half2 p1 = __floats2half2_rn(fmaxf(a1.x * id + b0.z, 0.f), fmaxf(a1.y * id + b0.w, 0.f));
    __half2 p2 = __floats2half2_rn(fmaxf(a2.x * id + b1.x, 0.f), fmaxf(a2.y * id + b1.y, 0.f));
    __half2 p3 = __floats2half2_rn(fmaxf(a3.x * id + b1.z, 0.f), fmaxf(a3.y * id + b1.w, 0.f));
    uint4 pk;
    pk.x = *(unsigned*)&p0; pk.y = *(unsigned*)&p1;
    pk.z = *(unsigned*)&p2; pk.w = *(unsigned*)&p3;
    ((uint4*)hout)[node * 8 + d8] = pk;
}

// -------- fused mean-pool + classifier: one block per graph --------
__global__ void k_poolclass(const __half* __restrict__ h, const int* __restrict__ gid,
                            const float* __restrict__ Wc, const float* __restrict__ bc,
                            float* __restrict__ out, int n, int C) {
    int g = blockIdx.x;
    __shared__ int sLo, sHi;
    if (threadIdx.x == 0) {
        int lo = 0, hi = n;
        while (lo < hi) { int m = (lo + hi) >> 1; if (gid[m] < g) lo = m + 1; else hi = m; }
        sLo = lo;
        int lo2 = lo, hi2 = n;
        while (lo2 < hi2) { int m = (lo2 + hi2) >> 1; if (gid[m] < g + 1) lo2 = m + 1; else hi2 = m; }
        sHi = lo2;
    }
    __syncthreads();
    int lo = sLo, hi = sHi;
    int d  = threadIdx.x & 63;
    int rg = threadIdx.x >> 6;               // 0..7 (512 threads)
    float acc = 0.f;
    for (int i = lo + rg; i < hi; i += 8) acc += __half2float(h[i * 64 + d]);
    __shared__ float sm[512];
    __shared__ float mean[64];
    sm[threadIdx.x] = acc;
    __syncthreads();
    if (threadIdx.x < 64) {
        float s = 0.f;
        #pragma unroll
        for (int k = 0; k < 8; ++k) s += sm[k * 64 + d];
        float cnt = (float)(hi - lo);
        mean[d] = s / fmaxf(cnt, 1.f);
    }
    __syncthreads();
    if ((int)threadIdx.x < C) {
        int c = threadIdx.x;
        float s = 0.f;
        #pragma unroll
        for (int dd = 0; dd < 64; ++dd) s += mean[dd] * Wc[dd * C + c];
        out[g * C + c] = s + bc[c];
    }
}

extern "C" void kernel_launch(void* const* d_in, const int* in_sizes, int n_in,
                              void* d_out, int out_size) {
    const int*   tokens   = (const int*)d_in[0];
    const int*   edge_src = (const int*)d_in[1];
    const int*   edge_dst = (const int*)d_in[2];
    const int*   graph_id = (const int*)d_in[3];
    const float* emb      = (const float*)d_in[4];
    const float* W1       = (const float*)d_in[5];
    const float* b1       = (const float*)d_in[6];
    const float* W2       = (const float*)d_in[7];
    const float* b2       = (const float*)d_in[8];
    const float* Wc       = (const float*)d_in[9];
    const float* bc       = (const float*)d_in[10];
    float* out = (float*)d_out;

    int N = in_sizes[0];
    int E = in_sizes[1];
    int C = in_sizes[10];
    int G = out_size / C;

    __half *tb, *hb;
    cudaGetSymbolAddress((void**)&tb, g_th);
    cudaGetSymbolAddress((void**)&hb, g_hh);

    int e8 = (E + 7) / 8;

    // Fork: GEMM-1 (fused embedding) on side stream, CSR build on main stream.
    cudaEventRecord(g_hx.evFork, 0);
    cudaStreamWaitEvent(g_hx.s2, g_hx.evFork, 0);
    k_gemm_mma<<<(N + 63) / 64, 128, 0, g_hx.s2>>>(nullptr, tokens, emb, W1, tb, N);
    cudaEventRecord(g_hx.evJoin, g_hx.s2);

    // CSR build (main stream)
    k_deg    <<<(e8 + 255) / 256, 256>>>(edge_dst, E);
    k_scan_a <<<NB_SCAN, 256>>>(N);
    k_scan_c <<<NB_SCAN, 256>>>(N, E);
    k_scatter<<<(e8 + 255) / 256, 256>>>(edge_src, edge_dst, E, N);

    // Join: agg-1 needs both CSR and GEMM-1 output.
    cudaStreamWaitEvent(0, g_hx.evJoin, 0);
    k_agg<<<(N + 31) / 32, 256>>>(tb, b1, hb, N);

    // layer 2
    k_gemm_mma<<<(N + 63) / 64, 128>>>(hb, nullptr, nullptr, W2, tb, N);
    k_agg<<<(N + 31) / 32, 256>>>(tb, b2, hb, N);

    // fused pool + classify
    k_poolclass<<<G, 512>>>(hb, graph_id, Wc, bc, out, N, C);
}